// round 13
// baseline (speedup 1.0000x reference)
#include <cuda_runtime.h>
#include <cuda_fp16.h>
#include <stdint.h>

#define BATCH   4096
#define IN_DIM  16384
#define OUT_DIM 16384
#define THREADS 512
#define PAIRS   (BATCH / 2)               // 2048
#define CTAS_PER_SM 3
#define JPT     (OUT_DIM / THREADS)       // 32 j per thread
#define NGROUP  (JPT / 2)                 // 16 groups of 2 consecutive j

// Per-j k coefficients, 8B: x = half2(k0,k1), y = half2(k2,k3)
__device__ uint2    g_k8[OUT_DIM];
// Per-j packed indices: a | (b<<16)
__device__ uint32_t g_idx_pack[OUT_DIM];
// Dynamic work queue counter
__device__ int g_ctr;

__constant__ float c_gate[16][4] = {
    {0.f, 0.f, 0.f, 0.f}, {0.f, 0.f, 0.f, 1.f}, {0.f, 1.f, 0.f,-1.f}, {0.f, 1.f, 0.f, 0.f},
    {0.f, 0.f, 1.f,-1.f}, {0.f, 0.f, 1.f, 0.f}, {0.f, 1.f, 1.f,-2.f}, {0.f, 1.f, 1.f,-1.f},
    {1.f,-1.f,-1.f, 1.f}, {1.f,-1.f,-1.f, 2.f}, {1.f, 0.f,-1.f, 0.f}, {1.f, 0.f,-1.f, 1.f},
    {1.f,-1.f, 0.f, 0.f}, {1.f,-1.f, 0.f, 1.f}, {1.f, 0.f, 0.f,-1.f}, {1.f, 0.f, 0.f, 0.f}
};

// int64-vs-int32 buffer detection (R1 fix).
__device__ __forceinline__ bool idx_is_int64(const int* p) {
    bool odd_all_zero = true;
    #pragma unroll
    for (int i = 1; i < 64; i += 2) odd_all_zero &= (p[i] == 0);
    return odd_all_zero;
}
__device__ __forceinline__ int load_index(const void* base, int j, bool is64) {
    if (is64) return (int)((const long long*)base)[j];
    return ((const int*)base)[j];
}

__global__ void prep_kernel(const float* __restrict__ w,
                            const void* __restrict__ a_idx,
                            const void* __restrict__ b_idx,
                            int ncta)
{
    int j = blockIdx.x * blockDim.x + threadIdx.x;
    if (j == 0) g_ctr = ncta;   // first ncta pairs statically assigned
    if (j >= OUT_DIM) return;

    const bool a64 = idx_is_int64((const int*)a_idx);
    const bool b64 = idx_is_int64((const int*)b_idx);

    float wv[16];
    const float4* w4 = reinterpret_cast<const float4*>(w + (size_t)j * 16);
    #pragma unroll
    for (int q = 0; q < 4; q++) {
        float4 v = __ldg(&w4[q]);
        wv[q*4+0] = v.x; wv[q*4+1] = v.y; wv[q*4+2] = v.z; wv[q*4+3] = v.w;
    }
    float m = wv[0];
    #pragma unroll
    for (int i = 1; i < 16; i++) m = fmaxf(m, wv[i]);
    float e[16], s = 0.f;
    #pragma unroll
    for (int i = 0; i < 16; i++) { e[i] = __expf(wv[i] - m); s += e[i]; }
    float inv = 1.0f / s;

    float k0 = 0.f, k1 = 0.f, k2 = 0.f, k3 = 0.f;
    #pragma unroll
    for (int i = 0; i < 16; i++) {
        float p = e[i] * inv;
        k0 = fmaf(p, c_gate[i][0], k0);
        k1 = fmaf(p, c_gate[i][1], k1);
        k2 = fmaf(p, c_gate[i][2], k2);
        k3 = fmaf(p, c_gate[i][3], k3);
    }

    unsigned int ia = (unsigned int)load_index(a_idx, j, a64);
    unsigned int ib = (unsigned int)load_index(b_idx, j, b64);

    __half2 h01 = __floats2half2_rn(k0, k1);
    __half2 h23 = __floats2half2_rn(k2, k3);
    uint2 k8;
    k8.x = *reinterpret_cast<unsigned int*>(&h01);
    k8.y = *reinterpret_cast<unsigned int*>(&h23);
    g_k8[j] = k8;
    g_idx_pack[j] = ia | (ib << 16);
}

__device__ __forceinline__ void prefetch_l2(const void* p) {
    asm volatile("prefetch.global.L2 [%0];" :: "l"(p));
}

// Evaluate one j for both rows of the pair.
__device__ __forceinline__ void eval2(uint32_t idxp, uint32_t k01u, uint32_t k23u,
                                      const __half2* __restrict__ xs,
                                      float& ve, float& vo)
{
    float2 k01 = __half22float2(*reinterpret_cast<__half2*>(&k01u));  // k0,k1
    float2 k23 = __half22float2(*reinterpret_cast<__half2*>(&k23u));  // k2,k3
    float2 a = __half22float2(xs[idxp & 0xFFFFu]);
    float2 b = __half22float2(xs[idxp >> 16]);
    ve = fmaf(a.x, fmaf(k23.y, b.x, k01.y), fmaf(k23.x, b.x, k01.x));
    vo = fmaf(a.y, fmaf(k23.y, b.y, k01.y), fmaf(k23.x, b.y, k01.x));
}

// Persistent kernel, 3 CTAs per SM (512 threads, 64KB smem each).
// Pair-interleaved half2 row slot, dynamic work queue, grouped-2 metadata
// loads and STG.64 stores. Throttled L2 prefetch of the next pair: first
// 64KB right after stage, second 64KB midway through compute — halves the
// live prefetch footprint vs R9's full-pair window (which thrashed L2).
__global__ void __launch_bounds__(THREADS, CTAS_PER_SM)
logic_main_kernel(const float* __restrict__ x, float* __restrict__ out)
{
    extern __shared__ __align__(16) unsigned char smem_raw[];
    __half2* xs = reinterpret_cast<__half2*>(smem_raw);   // 64KB: {even,odd} per col
    __shared__ int s_next;

    const int tid = threadIdx.x;
    int cur = blockIdx.x;

    // Prefetch first half of this CTA's first pair.
    if (cur < PAIRS) {
        const char* base = reinterpret_cast<const char*>(x + (size_t)(2 * cur) * IN_DIM);
        prefetch_l2(base + (size_t)tid * 128);
    }

    while (cur < PAIRS) {
        const float* __restrict__ r0 = x + (size_t)(2 * cur) * IN_DIM;

        // ---- stage: 2 fp32 rows -> interleaved half2 (16 independent LDG.128) ----
        #pragma unroll
        for (int it = 0; it < 8; it++) {
            int k = (tid + it * THREADS) * 4;
            float4 e = __ldcg(reinterpret_cast<const float4*>(r0 + k));
            float4 o = __ldcg(reinterpret_cast<const float4*>(r0 + IN_DIM + k));
            __half2 h0 = __floats2half2_rn(e.x, o.x);
            __half2 h1 = __floats2half2_rn(e.y, o.y);
            __half2 h2 = __floats2half2_rn(e.z, o.z);
            __half2 h3 = __floats2half2_rn(e.w, o.w);
            uint4 pk;
            pk.x = *reinterpret_cast<unsigned int*>(&h0);
            pk.y = *reinterpret_cast<unsigned int*>(&h1);
            pk.z = *reinterpret_cast<unsigned int*>(&h2);
            pk.w = *reinterpret_cast<unsigned int*>(&h3);
            *reinterpret_cast<uint4*>(xs + k) = pk;
        }
        // Pop next pair while staging drains.
        if (tid == 0) s_next = atomicAdd(&g_ctr, 1);
        __syncthreads();   // slot staged + s_next visible

        const int next = s_next;
        const char* nb = (next < PAIRS)
            ? reinterpret_cast<const char*>(x + (size_t)(2 * next) * IN_DIM) : nullptr;

        // Prefetch FIRST half (64KB) of the next pair now.
        if (nb) prefetch_l2(nb + (size_t)tid * 128);

        // ---- compute: both rows from the interleaved slot ----
        float* __restrict__ oe = out + (size_t)(2 * cur) * OUT_DIM;
        float* __restrict__ oo = oe + OUT_DIM;

        #pragma unroll
        for (int g = 0; g < NGROUP; g++) {
            // Prefetch SECOND half (64KB) midway through compute.
            if (g == NGROUP / 2) {
                if (nb) prefetch_l2(nb + (size_t)(tid + THREADS) * 128);
            }

            const int j0 = g * (OUT_DIM / NGROUP) + tid * 2;
            uint2 I = __ldg(reinterpret_cast<const uint2*>(&g_idx_pack[j0])); // 2 packed idx
            uint4 K = __ldg(reinterpret_cast<const uint4*>(&g_k8[j0]));       // k for j0,j0+1

            float2 ve, vo;
            eval2(I.x, K.x, K.y, xs, ve.x, vo.x);
            eval2(I.y, K.z, K.w, xs, ve.y, vo.y);

            __stcs(reinterpret_cast<float2*>(&oe[j0]), ve);
            __stcs(reinterpret_cast<float2*>(&oo[j0]), vo);
        }
        __syncthreads();   // protect slot before next stage
        cur = next;
    }
}

extern "C" void kernel_launch(void* const* d_in, const int* in_sizes, int n_in,
                              void* d_out, int out_size)
{
    const float* x  = (const float*)d_in[0];
    const float* w  = (const float*)d_in[1];
    const void*  ai = d_in[2];
    const void*  bi = d_in[3];
    float* out = (float*)d_out;
    (void)in_sizes; (void)n_in; (void)out_size;

    int nsm = 148;
    cudaDeviceGetAttribute(&nsm, cudaDevAttrMultiProcessorCount, 0);
    const int ncta = CTAS_PER_SM * nsm;

    const int smem_bytes = IN_DIM * sizeof(__half2);   // 64KB per CTA
    cudaFuncSetAttribute(logic_main_kernel,
                         cudaFuncAttributeMaxDynamicSharedMemorySize, smem_bytes);

    prep_kernel<<<(OUT_DIM + 511) / 512, 512>>>(w, ai, bi, ncta);
    logic_main_kernel<<<ncta, THREADS, smem_bytes>>>(x, out);
}

// round 14
// speedup vs baseline: 1.1767x; 1.1767x over previous
#include <cuda_runtime.h>
#include <cuda_fp16.h>
#include <stdint.h>

#define BATCH   4096
#define IN_DIM  16384
#define OUT_DIM 16384
#define THREADS 1024
#define PAIRS   (BATCH / 2)       // 2048
#define NGROUP  8                 // compute groups (2 j per thread each)
#define HALF_COLS 8192            // columns per convert half
#define CHUNK_BYTES 32768         // one row-half, fp32

// Per-j k coefficients, 8B: x = half2(k0,k1), y = half2(k2,k3)
__device__ uint2    g_k8[OUT_DIM];
// Per-j packed indices: a | (b<<16)
__device__ uint32_t g_idx_pack[OUT_DIM];
// Dynamic work queue counter
__device__ int g_ctr;

__constant__ float c_gate[16][4] = {
    {0.f, 0.f, 0.f, 0.f}, {0.f, 0.f, 0.f, 1.f}, {0.f, 1.f, 0.f,-1.f}, {0.f, 1.f, 0.f, 0.f},
    {0.f, 0.f, 1.f,-1.f}, {0.f, 0.f, 1.f, 0.f}, {0.f, 1.f, 1.f,-2.f}, {0.f, 1.f, 1.f,-1.f},
    {1.f,-1.f,-1.f, 1.f}, {1.f,-1.f,-1.f, 2.f}, {1.f, 0.f,-1.f, 0.f}, {1.f, 0.f,-1.f, 1.f},
    {1.f,-1.f, 0.f, 0.f}, {1.f,-1.f, 0.f, 1.f}, {1.f, 0.f, 0.f,-1.f}, {1.f, 0.f, 0.f, 0.f}
};

// int64-vs-int32 buffer detection (R1 fix).
__device__ __forceinline__ bool idx_is_int64(const int* p) {
    bool odd_all_zero = true;
    #pragma unroll
    for (int i = 1; i < 64; i += 2) odd_all_zero &= (p[i] == 0);
    return odd_all_zero;
}
__device__ __forceinline__ int load_index(const void* base, int j, bool is64) {
    if (is64) return (int)((const long long*)base)[j];
    return ((const int*)base)[j];
}

__global__ void prep_kernel(const float* __restrict__ w,
                            const void* __restrict__ a_idx,
                            const void* __restrict__ b_idx,
                            int ncta)
{
    int j = blockIdx.x * blockDim.x + threadIdx.x;
    if (j == 0) g_ctr = ncta;   // first ncta pairs statically assigned
    if (j >= OUT_DIM) return;

    const bool a64 = idx_is_int64((const int*)a_idx);
    const bool b64 = idx_is_int64((const int*)b_idx);

    float wv[16];
    const float4* w4 = reinterpret_cast<const float4*>(w + (size_t)j * 16);
    #pragma unroll
    for (int q = 0; q < 4; q++) {
        float4 v = __ldg(&w4[q]);
        wv[q*4+0] = v.x; wv[q*4+1] = v.y; wv[q*4+2] = v.z; wv[q*4+3] = v.w;
    }
    float m = wv[0];
    #pragma unroll
    for (int i = 1; i < 16; i++) m = fmaxf(m, wv[i]);
    float e[16], s = 0.f;
    #pragma unroll
    for (int i = 0; i < 16; i++) { e[i] = __expf(wv[i] - m); s += e[i]; }
    float inv = 1.0f / s;

    float k0 = 0.f, k1 = 0.f, k2 = 0.f, k3 = 0.f;
    #pragma unroll
    for (int i = 0; i < 16; i++) {
        float p = e[i] * inv;
        k0 = fmaf(p, c_gate[i][0], k0);
        k1 = fmaf(p, c_gate[i][1], k1);
        k2 = fmaf(p, c_gate[i][2], k2);
        k3 = fmaf(p, c_gate[i][3], k3);
    }

    unsigned int ia = (unsigned int)load_index(a_idx, j, a64);
    unsigned int ib = (unsigned int)load_index(b_idx, j, b64);

    __half2 h01 = __floats2half2_rn(k0, k1);
    __half2 h23 = __floats2half2_rn(k2, k3);
    uint2 k8;
    k8.x = *reinterpret_cast<unsigned int*>(&h01);
    k8.y = *reinterpret_cast<unsigned int*>(&h23);
    g_k8[j] = k8;
    g_idx_pack[j] = ia | (ib << 16);
}

// ---- mbarrier / TMA-bulk helpers (validated in R3) ----
__device__ __forceinline__ uint32_t smem_u32(const void* p) {
    uint32_t a;
    asm("{ .reg .u64 t; cvta.to.shared.u64 t, %1; cvt.u32.u64 %0, t; }" : "=r"(a) : "l"(p));
    return a;
}
__device__ __forceinline__ void mbar_init(uint32_t mbar, uint32_t cnt) {
    asm volatile("mbarrier.init.shared.b64 [%0], %1;" :: "r"(mbar), "r"(cnt) : "memory");
}
__device__ __forceinline__ void mbar_expect_tx(uint32_t mbar, uint32_t bytes) {
    asm volatile("mbarrier.arrive.expect_tx.shared.b64 _, [%0], %1;"
                 :: "r"(mbar), "r"(bytes) : "memory");
}
__device__ __forceinline__ void mbar_wait(uint32_t mbar, uint32_t phase) {
    asm volatile(
        "{\n\t.reg .pred P;\n\t"
        "WL_%=:\n\t"
        "mbarrier.try_wait.parity.acquire.cta.shared::cta.b64 P, [%0], %1, 0x989680;\n\t"
        "@P bra.uni WD_%=;\n\t"
        "bra.uni WL_%=;\n\t"
        "WD_%=:\n\t}"
        :: "r"(mbar), "r"(phase) : "memory");
}
__device__ __forceinline__ void bulk_g2s(uint32_t dst, const void* src, uint32_t bytes, uint32_t mbar) {
    asm volatile(
        "cp.async.bulk.shared::cta.global.mbarrier::complete_tx::bytes [%0], [%1], %2, [%3];"
        :: "r"(dst), "l"(src), "r"(bytes), "r"(mbar) : "memory");
}

// Issue the 4 TMA chunks for pair p: rows 2p (raw[0:16384]) and 2p+1
// (raw[16384:32768]); column-half h chunks complete on mbar[h].
__device__ __forceinline__ void issue_pair_tma(const float* x, int p,
                                               uint32_t raw_a, uint32_t mb0, uint32_t mb1)
{
    const float* r0 = x + (size_t)(2 * p) * IN_DIM;
    const float* r1 = r0 + IN_DIM;
    mbar_expect_tx(mb0, 2 * CHUNK_BYTES);
    mbar_expect_tx(mb1, 2 * CHUNK_BYTES);
    bulk_g2s(raw_a,                      r0,             CHUNK_BYTES, mb0); // r0 h0
    bulk_g2s(raw_a + CHUNK_BYTES,        r0 + HALF_COLS, CHUNK_BYTES, mb1); // r0 h1
    bulk_g2s(raw_a + 2 * CHUNK_BYTES,    r1,             CHUNK_BYTES, mb0); // r1 h0
    bulk_g2s(raw_a + 3 * CHUNK_BYTES,    r1 + HALF_COLS, CHUNK_BYTES, mb1); // r1 h1
}

// Convert column-half h of the raw fp32 pair into the half2-interleaved slot.
__device__ __forceinline__ void convert_half(const float* __restrict__ rawf,
                                             __half2* __restrict__ slot,
                                             int h, int tid)
{
    const int base = h * HALF_COLS;
    #pragma unroll
    for (int it = 0; it < HALF_COLS / (4 * THREADS); it++) {
        int k = base + (tid + it * THREADS) * 4;
        float4 e = *reinterpret_cast<const float4*>(rawf + k);           // row even
        float4 o = *reinterpret_cast<const float4*>(rawf + IN_DIM + k);  // row odd
        __half2 h0 = __floats2half2_rn(e.x, o.x);
        __half2 h1 = __floats2half2_rn(e.y, o.y);
        __half2 h2 = __floats2half2_rn(e.z, o.z);
        __half2 h3 = __floats2half2_rn(e.w, o.w);
        uint4 pk;
        pk.x = *reinterpret_cast<unsigned int*>(&h0);
        pk.y = *reinterpret_cast<unsigned int*>(&h1);
        pk.z = *reinterpret_cast<unsigned int*>(&h2);
        pk.w = *reinterpret_cast<unsigned int*>(&h3);
        *reinterpret_cast<uint4*>(slot + k) = pk;
    }
}

// Evaluate one j for both rows of the pair.
__device__ __forceinline__ void eval2(uint32_t idxp, uint32_t k01u, uint32_t k23u,
                                      const __half2* __restrict__ xs,
                                      float& ve, float& vo)
{
    float2 k01 = __half22float2(*reinterpret_cast<__half2*>(&k01u));  // k0,k1
    float2 k23 = __half22float2(*reinterpret_cast<__half2*>(&k23u));  // k2,k3
    float2 a = __half22float2(xs[idxp & 0xFFFFu]);
    float2 b = __half22float2(xs[idxp >> 16]);
    ve = fmaf(a.x, fmaf(k23.y, b.x, k01.y), fmaf(k23.x, b.x, k01.x));
    vo = fmaf(a.y, fmaf(k23.y, b.y, k01.y), fmaf(k23.x, b.y, k01.x));
}

// TMA-staged persistent kernel, 1 CTA/SM, 1024 threads.
// smem: 128KB raw fp32 TMA buffer + 64KB half2-interleaved slot + 2 mbarriers.
// Per pair: TMA engine streams the NEXT pair into raw during compute of the
// CURRENT pair (zero warp involvement); then warps convert raw -> slot.
// DRAM reads flow continuously, decoupled from warp phases.
__global__ void __launch_bounds__(THREADS, 1)
logic_main_kernel(const float* __restrict__ x, float* __restrict__ out)
{
    extern __shared__ __align__(16) unsigned char smem_raw[];
    float*   rawf = reinterpret_cast<float*>(smem_raw);                       // 128KB
    __half2* slot = reinterpret_cast<__half2*>(smem_raw + 4 * CHUNK_BYTES);   // 64KB
    uint32_t raw_a = smem_u32(rawf);
    uint32_t mb0   = smem_u32(smem_raw + 4 * CHUNK_BYTES + IN_DIM * sizeof(__half2));
    uint32_t mb1   = mb0 + 8;
    __shared__ int s_next;

    const int tid = threadIdx.x;

    if (tid == 0) {
        mbar_init(mb0, 1);
        mbar_init(mb1, 1);
        asm volatile("fence.proxy.async.shared::cta;" ::: "memory");
    }
    __syncthreads();

    int cur = blockIdx.x;
    uint32_t ph = 0;

    // Prologue: TMA pair `cur`, pop next, convert into slot.
    if (tid == 0) {
        issue_pair_tma(x, cur, raw_a, mb0, mb1);
        s_next = atomicAdd(&g_ctr, 1);
    }
    mbar_wait(mb0, 0);
    convert_half(rawf, slot, 0, tid);
    mbar_wait(mb1, 0);
    convert_half(rawf, slot, 1, tid);
    __syncthreads();           // raw consumed + slot ready + s_next visible
    int nxt = s_next;
    ph = 1;

    while (true) {
        const bool have_next = (nxt < PAIRS);
        if (tid == 0) {
            if (have_next) issue_pair_tma(x, nxt, raw_a, mb0, mb1);
            s_next = atomicAdd(&g_ctr, 1);   // pop pair-after-next
        }

        // ---- compute `cur` from slot (TMA streams `nxt` concurrently) ----
        float* __restrict__ oe = out + (size_t)(2 * cur) * OUT_DIM;
        float* __restrict__ oo = oe + OUT_DIM;

        #pragma unroll
        for (int g = 0; g < NGROUP; g++) {
            const int j0 = g * (OUT_DIM / NGROUP) + tid * 2;
            uint2 I = __ldg(reinterpret_cast<const uint2*>(&g_idx_pack[j0]));
            uint4 K = __ldg(reinterpret_cast<const uint4*>(&g_k8[j0]));

            float2 ve, vo;
            eval2(I.x, K.x, K.y, slot, ve.x, vo.x);
            eval2(I.y, K.z, K.w, slot, ve.y, vo.y);

            __stcs(reinterpret_cast<float2*>(&oe[j0]), ve);
            __stcs(reinterpret_cast<float2*>(&oo[j0]), vo);
        }
        __syncthreads();       // compute done: slot free, s_next visible
        if (!have_next) break;

        // ---- convert `nxt` raw -> slot (chunked waits overlap TMA tail) ----
        mbar_wait(mb0, ph & 1);
        convert_half(rawf, slot, 0, tid);
        mbar_wait(mb1, ph & 1);
        convert_half(rawf, slot, 1, tid);
        __syncthreads();       // raw fully consumed before next TMA issue

        cur = nxt;
        nxt = s_next;
        ph++;
    }
}

extern "C" void kernel_launch(void* const* d_in, const int* in_sizes, int n_in,
                              void* d_out, int out_size)
{
    const float* x  = (const float*)d_in[0];
    const float* w  = (const float*)d_in[1];
    const void*  ai = d_in[2];
    const void*  bi = d_in[3];
    float* out = (float*)d_out;
    (void)in_sizes; (void)n_in; (void)out_size;

    int nsm = 148;
    cudaDeviceGetAttribute(&nsm, cudaDevAttrMultiProcessorCount, 0);
    const int ncta = nsm;   // 1 CTA per SM

    // 128KB raw + 64KB slot + mbarriers
    const int smem_bytes = 4 * CHUNK_BYTES + IN_DIM * sizeof(__half2) + 64;
    cudaFuncSetAttribute(logic_main_kernel,
                         cudaFuncAttributeMaxDynamicSharedMemorySize, smem_bytes);

    prep_kernel<<<(OUT_DIM + 511) / 512, 512>>>(w, ai, bi, ncta);
    logic_main_kernel<<<ncta, THREADS, smem_bytes>>>(x, out);
}